// round 2
// baseline (speedup 1.0000x reference)
#include <cuda_runtime.h>
#include <cuda_bf16.h>
#include <cstdint>

// Problem constants
#define B_   128
#define L_   336
#define N_   321
#define E_   128
#define LAT_ 64

// Output layout (flat, in reference return order): h, h_hat, mu, var
#define H_SZ    (B_ * N_ * E_)      // 5,259,264
#define MU_SZ   (B_ * N_ * LAT_)    // 2,629,632
#define OFF_H   0
#define OFF_HH  (H_SZ)              // 5,259,264
#define OFF_MU  (2 * H_SZ)          // 10,518,528
#define OFF_VAR (2 * H_SZ + MU_SZ)  // 13,148,160

// Scratch: x transposed to [N][B][L] so per-channel GEMM A-reads are contiguous.
__device__ float g_xp[(size_t)N_ * B_ * L_];

// ---------------------------------------------------------------------------
// Packed fp32x2 FMA (sm_100+): double-rate fp32
// ---------------------------------------------------------------------------
union F2U { float2 f; unsigned long long u; };
__device__ __forceinline__ float2 ffma2(float2 a, float2 b, float2 c) {
    F2U A, Bv, C;
    A.f = a; Bv.f = b; C.f = c;
    asm("fma.rn.f32x2 %0, %1, %2, %3;"
        : "=l"(C.u) : "l"(A.u), "l"(Bv.u), "l"(C.u));
    return C.f;
}

// ---------------------------------------------------------------------------
// Kernel 1: transpose x [B, L, N] -> xp [N, B, L]
// ---------------------------------------------------------------------------
__global__ void transpose_kernel(const float* __restrict__ x, float* __restrict__ xp) {
    __shared__ float t[32][33];
    const int b  = blockIdx.z;
    const int n0 = blockIdx.x * 32;
    const int l0 = blockIdx.y * 32;
    const int tx = threadIdx.x, ty = threadIdx.y;

    const float* xb = x + (size_t)b * L_ * N_;
#pragma unroll
    for (int i = 0; i < 32; i += 8) {
        int l = l0 + ty + i, nn = n0 + tx;
        if (l < L_ && nn < N_)
            t[ty + i][tx] = xb[l * N_ + nn];
    }
    __syncthreads();
#pragma unroll
    for (int i = 0; i < 32; i += 8) {
        int nn = n0 + ty + i, l = l0 + tx;
        if (nn < N_ && l < L_)
            xp[(size_t)nn * B_ * L_ + b * L_ + l] = t[tx][ty + i];
    }
}

// ---------------------------------------------------------------------------
// Kernel 2: per-channel GEMM1 + bias + sigmoid gate.
//   h[b,n,e]  = sum_l xp[n,b,l] * W_embed[n,l,e] + b_embed[n,e]
//   hh[b,n,e] = sigmoid(time_x[b,n,e]) * h
// One CTA per channel n: C tile 128x128, K=336 (21 x BK=16), double-buffered.
// ---------------------------------------------------------------------------
#define BK 16

__global__ __launch_bounds__(256, 2)
void gemm1_kernel(const float* __restrict__ xp,
                  const float* __restrict__ We,    // [N][L][E]
                  const float* __restrict__ be,    // [N][E]
                  const float* __restrict__ txg,   // [B][N][E]
                  float* __restrict__ out)
{
    const int n = blockIdx.x;
    const float* A  = xp + (size_t)n * B_ * L_;   // row stride L_
    const float* Bw = We + (size_t)n * L_ * E_;   // row stride E_

    __shared__ float As[2][BK][128];
    __shared__ float Bs[2][BK][128];

    const int tid = threadIdx.x;
    const int tx = tid & 15, ty = tid >> 4;

    float4 ra[2], rb[2];
    float2 c[8][4];
#pragma unroll
    for (int i = 0; i < 8; i++)
#pragma unroll
        for (int j = 0; j < 4; j++) c[i][j] = make_float2(0.f, 0.f);

    auto ldg = [&](int kt) {
        const int k0 = kt * BK;
#pragma unroll
        for (int i = 0; i < 2; i++) {
            int idx = tid + i * 256;
            int m = idx >> 2, c4 = (idx & 3) * 4;
            ra[i] = *(const float4*)(A + m * L_ + k0 + c4);
            int r = idx >> 5, e4 = (idx & 31) * 4;
            rb[i] = *(const float4*)(Bw + (k0 + r) * E_ + e4);
        }
    };
    auto sts = [&](int buf) {
#pragma unroll
        for (int i = 0; i < 2; i++) {
            int idx = tid + i * 256;
            int m = idx >> 2, c4 = (idx & 3) * 4;
            As[buf][c4 + 0][m] = ra[i].x;
            As[buf][c4 + 1][m] = ra[i].y;
            As[buf][c4 + 2][m] = ra[i].z;
            As[buf][c4 + 3][m] = ra[i].w;
            int r = idx >> 5, e4 = (idx & 31) * 4;
            *(float4*)&Bs[buf][r][e4] = rb[i];
        }
    };

    ldg(0); sts(0);
    __syncthreads();

    const int NT = L_ / BK;  // 21
    for (int kt = 0; kt < NT; kt++) {
        const int cur = kt & 1;
        if (kt + 1 < NT) ldg(kt + 1);
#pragma unroll
        for (int k = 0; k < BK; k++) {
            float a[8]; float2 b2[4];
            *(float4*)&a[0]  = *(const float4*)&As[cur][k][ty * 8];
            *(float4*)&a[4]  = *(const float4*)&As[cur][k][ty * 8 + 4];
            *(float4*)&b2[0] = *(const float4*)&Bs[cur][k][tx * 8];
            *(float4*)&b2[2] = *(const float4*)&Bs[cur][k][tx * 8 + 4];
#pragma unroll
            for (int i = 0; i < 8; i++) {
                float2 ap = make_float2(a[i], a[i]);
#pragma unroll
                for (int j = 0; j < 4; j++)
                    c[i][j] = ffma2(ap, b2[j], c[i][j]);
            }
        }
        if (kt + 1 < NT) { sts(cur ^ 1); }
        __syncthreads();
    }

    // Epilogue: bias, write h; sigmoid gate with time_x, write h_hat.
    const int mbase = ty * 8;
    const int ebase = tx * 8;
    float bv[8];
    *(float4*)&bv[0] = *(const float4*)(be + n * E_ + ebase);
    *(float4*)&bv[4] = *(const float4*)(be + n * E_ + ebase + 4);

    float* out_h  = out + OFF_H;
    float* out_hh = out + OFF_HH;
#pragma unroll
    for (int i = 0; i < 8; i++) {
        const int b = mbase + i;
        const int o = b * (N_ * E_) + n * E_ + ebase;
        float h[8];
        h[0] = c[i][0].x + bv[0]; h[1] = c[i][0].y + bv[1];
        h[2] = c[i][1].x + bv[2]; h[3] = c[i][1].y + bv[3];
        h[4] = c[i][2].x + bv[4]; h[5] = c[i][2].y + bv[5];
        h[6] = c[i][3].x + bv[6]; h[7] = c[i][3].y + bv[7];
        *(float4*)(out_h + o)     = *(float4*)&h[0];
        *(float4*)(out_h + o + 4) = *(float4*)&h[4];

        float t[8];
        *(float4*)&t[0] = *(const float4*)(txg + o);
        *(float4*)&t[4] = *(const float4*)(txg + o + 4);
        float hh[8];
#pragma unroll
        for (int j = 0; j < 8; j++) {
            float s = 1.0f / (1.0f + __expf(-t[j]));
            hh[j] = s * h[j];
        }
        *(float4*)(out_hh + o)     = *(float4*)&hh[0];
        *(float4*)(out_hh + o + 4) = *(float4*)&hh[4];
    }
}

// ---------------------------------------------------------------------------
// Kernel 3: per-channel GEMM2/3 fused:
//   mu[b,n,k]  = sum_e hh[b,n,e] * W_mu[n,e,k]  + b_mu[n,k]
//   var[b,n,k] = sum_e hh[b,n,e] * W_var[n,e,k] + b_var[n,k]
// Weight concatenated along output dim: cols [0,64) = mu, [64,128) = var.
// A = h_hat read from d_out (row stride N_*E_). K = E_ = 128 (8 k-tiles).
// ---------------------------------------------------------------------------
__global__ __launch_bounds__(256, 2)
void gemm2_kernel(const float* __restrict__ outc,  // = d_out (reads h_hat region)
                  const float* __restrict__ Wmu,   // [N][E][LAT]
                  const float* __restrict__ bmu,   // [N][LAT]
                  const float* __restrict__ Wvar,  // [N][E][LAT]
                  const float* __restrict__ bvar,  // [N][LAT]
                  float* __restrict__ out)
{
    const int n = blockIdx.x;
    const float* A = outc + OFF_HH + n * E_;      // row stride N_*E_
    const float* Wm = Wmu  + (size_t)n * E_ * LAT_;
    const float* Wv = Wvar + (size_t)n * E_ * LAT_;

    __shared__ float As[2][BK][128];
    __shared__ float Bs[2][BK][128];

    const int tid = threadIdx.x;
    const int tx = tid & 15, ty = tid >> 4;

    float4 ra[2], rb[2];
    float2 c[8][4];
#pragma unroll
    for (int i = 0; i < 8; i++)
#pragma unroll
        for (int j = 0; j < 4; j++) c[i][j] = make_float2(0.f, 0.f);

    auto ldg = [&](int kt) {
        const int k0 = kt * BK;
#pragma unroll
        for (int i = 0; i < 2; i++) {
            int idx = tid + i * 256;
            int m = idx >> 2, c4 = (idx & 3) * 4;
            ra[i] = *(const float4*)(A + m * (N_ * E_) + k0 + c4);
            int r = idx >> 5, j4 = (idx & 31) * 4;   // j4: output col
            const int e = k0 + r;
            const float* src = (j4 < 64) ? (Wm + e * LAT_ + j4)
                                         : (Wv + e * LAT_ + (j4 - 64));
            rb[i] = *(const float4*)src;
        }
    };
    auto sts = [&](int buf) {
#pragma unroll
        for (int i = 0; i < 2; i++) {
            int idx = tid + i * 256;
            int m = idx >> 2, c4 = (idx & 3) * 4;
            As[buf][c4 + 0][m] = ra[i].x;
            As[buf][c4 + 1][m] = ra[i].y;
            As[buf][c4 + 2][m] = ra[i].z;
            As[buf][c4 + 3][m] = ra[i].w;
            int r = idx >> 5, j4 = (idx & 31) * 4;
            *(float4*)&Bs[buf][r][j4] = rb[i];
        }
    };

    ldg(0); sts(0);
    __syncthreads();

    const int NT = E_ / BK;  // 8
    for (int kt = 0; kt < NT; kt++) {
        const int cur = kt & 1;
        if (kt + 1 < NT) ldg(kt + 1);
#pragma unroll
        for (int k = 0; k < BK; k++) {
            float a[8]; float2 b2[4];
            *(float4*)&a[0]  = *(const float4*)&As[cur][k][ty * 8];
            *(float4*)&a[4]  = *(const float4*)&As[cur][k][ty * 8 + 4];
            *(float4*)&b2[0] = *(const float4*)&Bs[cur][k][tx * 8];
            *(float4*)&b2[2] = *(const float4*)&Bs[cur][k][tx * 8 + 4];
#pragma unroll
            for (int i = 0; i < 8; i++) {
                float2 ap = make_float2(a[i], a[i]);
#pragma unroll
                for (int j = 0; j < 4; j++)
                    c[i][j] = ffma2(ap, b2[j], c[i][j]);
            }
        }
        if (kt + 1 < NT) { sts(cur ^ 1); }
        __syncthreads();
    }

    // Epilogue: cols [0,64) -> mu, [64,128) -> var. Each thread owns 8
    // consecutive cols entirely inside one of the two halves.
    const int mbase = ty * 8;
    const int jfull = tx * 8;
    const bool is_mu = (jfull < 64);
    const int jb = is_mu ? jfull : (jfull - 64);
    const float* bp = (is_mu ? bmu : bvar) + n * LAT_ + jb;
    const int OFFO = is_mu ? OFF_MU : OFF_VAR;

    float bv[8];
    *(float4*)&bv[0] = *(const float4*)(bp);
    *(float4*)&bv[4] = *(const float4*)(bp + 4);

#pragma unroll
    for (int i = 0; i < 8; i++) {
        const int b = mbase + i;
        const int o = OFFO + b * (N_ * LAT_) + n * LAT_ + jb;
        float v[8];
        v[0] = c[i][0].x + bv[0]; v[1] = c[i][0].y + bv[1];
        v[2] = c[i][1].x + bv[2]; v[3] = c[i][1].y + bv[3];
        v[4] = c[i][2].x + bv[4]; v[5] = c[i][2].y + bv[5];
        v[6] = c[i][3].x + bv[6]; v[7] = c[i][3].y + bv[7];
        *(float4*)(out + o)     = *(float4*)&v[0];
        *(float4*)(out + o + 4) = *(float4*)&v[4];
    }
}

// ---------------------------------------------------------------------------
extern "C" void kernel_launch(void* const* d_in, const int* in_sizes, int n_in,
                              void* d_out, int out_size) {
    const float* x    = (const float*)d_in[0];
    const float* txg  = (const float*)d_in[1];
    const float* We   = (const float*)d_in[2];
    const float* be   = (const float*)d_in[3];
    const float* Wmu  = (const float*)d_in[4];
    const float* bmu  = (const float*)d_in[5];
    const float* Wvar = (const float*)d_in[6];
    const float* bvar = (const float*)d_in[7];
    float* out = (float*)d_out;

    float* xp;
    cudaGetSymbolAddress((void**)&xp, g_xp);

    dim3 tgrid((N_ + 31) / 32, (L_ + 31) / 32, B_);
    transpose_kernel<<<tgrid, dim3(32, 8)>>>(x, xp);
    gemm1_kernel<<<N_, 256>>>(xp, We, be, txg, out);
    gemm2_kernel<<<N_, 256>>>(out, Wmu, bmu, Wvar, bvar, out);
}

// round 4
// speedup vs baseline: 1.3045x; 1.3045x over previous
#include <cuda_runtime.h>
#include <cstdint>

#define B_   128
#define L_   336
#define LP   352
#define N_   321
#define E_   128
#define LAT_ 64

#define H_SZ    (B_ * N_ * E_)
#define MU_SZ   (B_ * N_ * LAT_)
#define OFF_H   0
#define OFF_HH  (H_SZ)
#define OFF_MU  (2 * H_SZ)
#define OFF_VAR (2 * H_SZ + MU_SZ)

__device__ float g_xp [(size_t)N_ * B_ * LP];     // [n][b][l], zero-padded to LP
__device__ float g_wt [(size_t)N_ * E_ * LP];     // [n][e][l] = W_embed^T, padded
__device__ float g_w2t[(size_t)N_ * 128 * E_];    // [n][j][e]; j<64: W_mu^T, j>=64: W_var^T

// ---------------- helpers ----------------
static __device__ __forceinline__ uint32_t s2u(const void* p) {
    uint32_t a;
    asm("{ .reg .u64 t; cvta.to.shared.u64 t, %1; cvt.u32.u64 %0, t; }" : "=r"(a) : "l"(p));
    return a;
}
#define CP16(d, s)  asm volatile("cp.async.cg.shared.global [%0], [%1], 16;" :: "r"(d), "l"(s))
#define CP_COMMIT() asm volatile("cp.async.commit_group;" ::: "memory")
#define CP_WAIT1()  asm volatile("cp.async.wait_group 1;" ::: "memory")
#define CP_WAIT0()  asm volatile("cp.async.wait_group 0;" ::: "memory")

static __device__ __forceinline__ uint32_t to_tf32(float f) {
    uint32_t u;
    asm("cvt.rna.tf32.f32 %0, %1;" : "=r"(u) : "f"(f));
    return u;
}
static __device__ __forceinline__ void mma_tf32(float c[4],
                                                uint32_t a0, uint32_t a1, uint32_t a2, uint32_t a3,
                                                uint32_t b0, uint32_t b1) {
    asm volatile("mma.sync.aligned.m16n8k8.row.col.f32.tf32.tf32.f32 "
                 "{%0,%1,%2,%3}, {%4,%5,%6,%7}, {%8,%9}, {%0,%1,%2,%3};"
                 : "+f"(c[0]), "+f"(c[1]), "+f"(c[2]), "+f"(c[3])
                 : "r"(a0), "r"(a1), "r"(a2), "r"(a3), "r"(b0), "r"(b1));
}

// ---------------- transposes ----------------
__global__ void t1_kernel(const float* __restrict__ x, float* __restrict__ xp) {
    __shared__ float t[32][33];
    const int b = blockIdx.z, n0 = blockIdx.x * 32, l0 = blockIdx.y * 32;
    const int tx = threadIdx.x, ty = threadIdx.y;
    const float* xb = x + (size_t)b * L_ * N_;
#pragma unroll
    for (int i = 0; i < 32; i += 8) {
        int l = l0 + ty + i, nn = n0 + tx;
        t[ty + i][tx] = (l < L_ && nn < N_) ? xb[l * N_ + nn] : 0.f;
    }
    __syncthreads();
#pragma unroll
    for (int i = 0; i < 32; i += 8) {
        int nn = n0 + ty + i, l = l0 + tx;
        if (nn < N_) xp[(size_t)nn * B_ * LP + b * LP + l] = t[tx][ty + i];
    }
}
__global__ void t2_kernel(const float* __restrict__ We, float* __restrict__ wt) {
    __shared__ float t[32][33];
    const int n = blockIdx.x, l0 = blockIdx.y * 32, e0 = blockIdx.z * 32;
    const int tx = threadIdx.x, ty = threadIdx.y;
    const float* src = We + (size_t)n * L_ * E_;
#pragma unroll
    for (int i = 0; i < 32; i += 8) {
        int l = l0 + ty + i;
        t[ty + i][tx] = (l < L_) ? src[l * E_ + e0 + tx] : 0.f;
    }
    __syncthreads();
    float* dst = wt + (size_t)n * E_ * LP;
#pragma unroll
    for (int i = 0; i < 32; i += 8)
        dst[(e0 + ty + i) * LP + l0 + tx] = t[tx][ty + i];
}
__global__ void t3_kernel(const float* __restrict__ Wmu, const float* __restrict__ Wvar,
                          float* __restrict__ w2t) {
    __shared__ float t[32][33];
    const int n = blockIdx.x, j0 = blockIdx.y * 32, e0 = blockIdx.z * 32;
    const int tx = threadIdx.x, ty = threadIdx.y;
    const float* src = ((j0 < 64) ? Wmu : Wvar) + (size_t)n * E_ * LAT_;
    const int jb = j0 & 63;
#pragma unroll
    for (int i = 0; i < 32; i += 8)
        t[ty + i][tx] = src[(e0 + ty + i) * LAT_ + jb + tx];
    __syncthreads();
    float* dst = w2t + (size_t)n * 128 * E_;
#pragma unroll
    for (int i = 0; i < 32; i += 8)
        dst[(j0 + ty + i) * E_ + e0 + tx] = t[tx][ty + i];
}

// ---------------- fused per-channel kernel ----------------
// smem (floats):
//   mainloop: bufA[2] @0/4608, bufB[2] @9216/13824 (each 128 rows x stride 36)
//   stage/A2: @0, 128 rows x stride 132 (16896 floats)  [after mainloop]
//   B2      : @18432, 128 rows x stride 132
#define SA    36
#define S2    132
#define NC1   11
#define F_A0  0
#define F_A1  4608
#define F_B0  9216
#define F_B1  13824
#define F_B2  18432
#define SM_FLOATS (F_B2 + 128 * S2)          // 35328 floats
#define SM_BYTES  (SM_FLOATS * 4)            // 141312 B

__global__ __launch_bounds__(256, 1)
void fused_kernel(const float* __restrict__ xp, const float* __restrict__ wt,
                  const float* __restrict__ w2t,
                  const float* __restrict__ be, const float* __restrict__ txg,
                  const float* __restrict__ bmu, const float* __restrict__ bvar,
                  float* __restrict__ out)
{
    extern __shared__ float sm[];
    const uint32_t sb = s2u(sm);
    const int tid = threadIdx.x, wid = tid >> 5, lane = tid & 31;
    const int g = lane >> 2, tg = lane & 3;
    const int n = blockIdx.x;
    const int m0 = (wid & 3) * 32;     // warp m-tile base
    const int n0 = (wid >> 2) * 64;    // warp n-tile base

    const float* Abase = xp + (size_t)n * B_ * LP;
    const float* Bbase = wt + (size_t)n * E_ * LP;

    const uint32_t aOff[2] = {F_A0 * 4u, F_A1 * 4u};
    const uint32_t bOff[2] = {F_B0 * 4u, F_B1 * 4u};

    auto load_chunk = [&](int c, int buf) {
        const float* As = Abase + c * 32;
        const float* Bs = Bbase + c * 32;
#pragma unroll
        for (int i = 0; i < 8; i++) {
            int op = tid + i * 256;            // 0..2047
            int isB = op >> 10, q = op & 1023; // 128 rows x 8 segs
            int row = q >> 3, seg = q & 7;
            const float* src = (isB ? Bs : As) + row * LP + seg * 4;
            uint32_t dst = sb + (isB ? bOff[buf] : aOff[buf]) + (uint32_t)(row * SA + seg * 4) * 4u;
            CP16(dst, src);
        }
        CP_COMMIT();
    };

    float acc[2][8][4];
#pragma unroll
    for (int mi = 0; mi < 2; mi++)
#pragma unroll
        for (int ni = 0; ni < 8; ni++)
#pragma unroll
            for (int r = 0; r < 4; r++) acc[mi][ni][r] = 0.f;

    load_chunk(0, 0);
    load_chunk(1, 1);

    for (int c = 0; c < NC1; c++) {
        const int buf = c & 1;
        if (c + 1 < NC1) CP_WAIT1(); else CP_WAIT0();
        __syncthreads();
        const float* As = sm + (buf ? F_A1 : F_A0);
        const float* Bs = sm + (buf ? F_B1 : F_B0);
#pragma unroll
        for (int s = 0; s < 4; s++) {
            const int k0 = s * 8;
            uint32_t af[2][4];
#pragma unroll
            for (int mi = 0; mi < 2; mi++) {
                const int r0 = m0 + mi * 16 + g;
                af[mi][0] = to_tf32(As[r0 * SA + k0 + tg]);
                af[mi][1] = to_tf32(As[(r0 + 8) * SA + k0 + tg]);
                af[mi][2] = to_tf32(As[r0 * SA + k0 + tg + 4]);
                af[mi][3] = to_tf32(As[(r0 + 8) * SA + k0 + tg + 4]);
            }
#pragma unroll
            for (int ni = 0; ni < 8; ni++) {
                const int nr = n0 + ni * 8 + g;
                uint32_t b0 = to_tf32(Bs[nr * SA + k0 + tg]);
                uint32_t b1 = to_tf32(Bs[nr * SA + k0 + tg + 4]);
#pragma unroll
                for (int mi = 0; mi < 2; mi++)
                    mma_tf32(acc[mi][ni], af[mi][0], af[mi][1], af[mi][2], af[mi][3], b0, b1);
            }
        }
        __syncthreads();
        if (c + 2 < NC1) load_chunk(c + 2, buf);
    }

    // kick off B2 (w2t tile) load into F_B2 while we do epilogue 1
    {
        const float* Bsrc = w2t + (size_t)n * 128 * E_;
#pragma unroll
        for (int i = 0; i < 16; i++) {
            int op = tid + i * 256;           // 128 rows x 32 segs
            int row = op >> 5, seg = op & 31;
            uint32_t dst = sb + (uint32_t)(F_B2 + row * S2 + seg * 4) * 4u;
            CP16(dst, Bsrc + row * E_ + seg * 4);
        }
        CP_COMMIT();
    }

    // stage GEMM1 C into smem (raw, no bias)
#pragma unroll
    for (int mi = 0; mi < 2; mi++) {
        const int r0 = m0 + mi * 16 + g;
#pragma unroll
        for (int ni = 0; ni < 8; ni++) {
            const int col = n0 + ni * 8 + 2 * tg;
            *(float2*)&sm[r0 * S2 + col]       = make_float2(acc[mi][ni][0], acc[mi][ni][1]);
            *(float2*)&sm[(r0 + 8) * S2 + col] = make_float2(acc[mi][ni][2], acc[mi][ni][3]);
        }
    }
    __syncthreads();

    // epilogue 1: h = C + bias -> gmem; hh = h*sigmoid(tx) -> gmem + back into stage
    float* out_h  = out + OFF_H;
    float* out_hh = out + OFF_HH;
#pragma unroll
    for (int i = 0; i < 16; i++) {
        int q = tid + i * 256;                // 128 rows x 32 quads
        int b = q >> 5, e = (q & 31) * 4;
        const int o = b * (N_ * E_) + n * E_ + e;
        float4 bv = *(const float4*)(be + n * E_ + e);
        float* sp = sm + b * S2 + e;
        float4 h;
        h.x = sp[0] + bv.x; h.y = sp[1] + bv.y; h.z = sp[2] + bv.z; h.w = sp[3] + bv.w;
        *(float4*)(out_h + o) = h;
        float4 t = *(const float4*)(txg + o);
        float4 gg;
        gg.x = h.x / (1.f + __expf(-t.x));
        gg.y = h.y / (1.f + __expf(-t.y));
        gg.z = h.z / (1.f + __expf(-t.z));
        gg.w = h.w / (1.f + __expf(-t.w));
        *(float4*)(out_hh + o) = gg;
        sp[0] = gg.x; sp[1] = gg.y; sp[2] = gg.z; sp[3] = gg.w;
    }
    CP_WAIT0();
    __syncthreads();

    // GEMM2: C2[b][j] = hh @ w2t^T, K = 128
    float acc2[2][8][4];
#pragma unroll
    for (int mi = 0; mi < 2; mi++)
#pragma unroll
        for (int ni = 0; ni < 8; ni++)
#pragma unroll
            for (int r = 0; r < 4; r++) acc2[mi][ni][r] = 0.f;

    const float* A2 = sm;            // [b][e] stride S2
    const float* B2 = sm + F_B2;     // [j][e] stride S2
#pragma unroll
    for (int s = 0; s < 16; s++) {
        const int k0 = s * 8;
        uint32_t af[2][4];
#pragma unroll
        for (int mi = 0; mi < 2; mi++) {
            const int r0 = m0 + mi * 16 + g;
            af[mi][0] = to_tf32(A2[r0 * S2 + k0 + tg]);
            af[mi][1] = to_tf32(A2[(r0 + 8) * S2 + k0 + tg]);
            af[mi][2] = to_tf32(A2[r0 * S2 + k0 + tg + 4]);
            af[mi][3] = to_tf32(A2[(r0 + 8) * S2 + k0 + tg + 4]);
        }
#pragma unroll
        for (int ni = 0; ni < 8; ni++) {
            const int nr = n0 + ni * 8 + g;
            uint32_t b0 = to_tf32(B2[nr * S2 + k0 + tg]);
            uint32_t b1 = to_tf32(B2[nr * S2 + k0 + tg + 4]);
#pragma unroll
            for (int mi = 0; mi < 2; mi++)
                mma_tf32(acc2[mi][ni], af[mi][0], af[mi][1], af[mi][2], af[mi][3], b0, b1);
        }
    }
    __syncthreads();

    // stage GEMM2 C
#pragma unroll
    for (int mi = 0; mi < 2; mi++) {
        const int r0 = m0 + mi * 16 + g;
#pragma unroll
        for (int ni = 0; ni < 8; ni++) {
            const int col = n0 + ni * 8 + 2 * tg;
            *(float2*)&sm[r0 * S2 + col]       = make_float2(acc2[mi][ni][0], acc2[mi][ni][1]);
            *(float2*)&sm[(r0 + 8) * S2 + col] = make_float2(acc2[mi][ni][2], acc2[mi][ni][3]);
        }
    }
    __syncthreads();

    // epilogue 2: j<64 -> mu, j>=64 -> var (+bias)
#pragma unroll
    for (int i = 0; i < 16; i++) {
        int q = tid + i * 256;
        int b = q >> 5, j = (q & 31) * 4;
        const int is_mu = (j < 64);
        const int jb = j & 63;
        const float* bp = (is_mu ? bmu : bvar) + n * LAT_ + jb;
        float4 bv = *(const float4*)bp;
        float* sp = sm + b * S2 + j;
        float4 v;
        v.x = sp[0] + bv.x; v.y = sp[1] + bv.y; v.z = sp[2] + bv.z; v.w = sp[3] + bv.w;
        const int o = (is_mu ? OFF_MU : OFF_VAR) + b * (N_ * LAT_) + n * LAT_ + jb;
        *(float4*)(out + o) = v;
    }
}

// ---------------- launch ----------------
extern "C" void kernel_launch(void* const* d_in, const int* in_sizes, int n_in,
                              void* d_out, int out_size) {
    const float* x    = (const float*)d_in[0];
    const float* txg  = (const float*)d_in[1];
    const float* We   = (const float*)d_in[2];
    const float* be   = (const float*)d_in[3];
    const float* Wmu  = (const float*)d_in[4];
    const float* bmu  = (const float*)d_in[5];
    const float* Wvar = (const float*)d_in[6];
    const float* bvar = (const float*)d_in[7];
    float* out = (float*)d_out;

    float *xp, *wt, *w2t;
    cudaGetSymbolAddress((void**)&xp,  g_xp);
    cudaGetSymbolAddress((void**)&wt,  g_wt);
    cudaGetSymbolAddress((void**)&w2t, g_w2t);

    cudaFuncSetAttribute(fused_kernel, cudaFuncAttributeMaxDynamicSharedMemorySize, SM_BYTES);

    t1_kernel<<<dim3(11, 11, B_), dim3(32, 8)>>>(x, xp);
    t2_kernel<<<dim3(N_, 11, 4), dim3(32, 8)>>>(We, wt);
    t3_kernel<<<dim3(N_, 4, 4), dim3(32, 8)>>>(Wmu, Wvar, w2t);
    fused_kernel<<<N_, 256, SM_BYTES>>>(xp, wt, w2t, be, txg, bmu, bvar, out);
}

// round 5
// speedup vs baseline: 2.1007x; 1.6103x over previous
#include <cuda_runtime.h>
#include <cstdint>

#define B_   128
#define L_   336
#define LP   352
#define N_   321
#define E_   128
#define LAT_ 64
#define NE_  (N_ * E_)
#define NL_  (N_ * LAT_)

#define H_SZ    (B_ * N_ * E_)
#define MU_SZ   (B_ * N_ * LAT_)
#define OFF_H   0
#define OFF_HH  (H_SZ)
#define OFF_MU  (2 * H_SZ)
#define OFF_VAR (2 * H_SZ + MU_SZ)

__device__ float g_xp[(size_t)N_ * B_ * LP];   // [n][b][l], zero-padded to LP

// ---------------- helpers ----------------
static __device__ __forceinline__ uint32_t s2u(const void* p) {
    uint32_t a;
    asm("{ .reg .u64 t; cvta.to.shared.u64 t, %1; cvt.u32.u64 %0, t; }" : "=r"(a) : "l"(p));
    return a;
}
#define CP16(d, s)      asm volatile("cp.async.cg.shared.global [%0], [%1], 16;" :: "r"(d), "l"(s))
#define CP16Z(d, s, sz) asm volatile("cp.async.cg.shared.global [%0], [%1], 16, %2;" :: "r"(d), "l"(s), "r"(sz))
#define CP_COMMIT() asm volatile("cp.async.commit_group;" ::: "memory")
#define CP_WAIT1()  asm volatile("cp.async.wait_group 1;" ::: "memory")
#define CP_WAIT0()  asm volatile("cp.async.wait_group 0;" ::: "memory")

static __device__ __forceinline__ uint32_t to_tf32(float f) {
    uint32_t u;
    asm("cvt.rna.tf32.f32 %0, %1;" : "=r"(u) : "f"(f));
    return u;
}
static __device__ __forceinline__ void mma_tf32(float c[4],
                                                uint32_t a0, uint32_t a1, uint32_t a2, uint32_t a3,
                                                uint32_t b0, uint32_t b1) {
    asm volatile("mma.sync.aligned.m16n8k8.row.col.f32.tf32.tf32.f32 "
                 "{%0,%1,%2,%3}, {%4,%5,%6,%7}, {%8,%9}, {%0,%1,%2,%3};"
                 : "+f"(c[0]), "+f"(c[1]), "+f"(c[2]), "+f"(c[3])
                 : "r"(a0), "r"(a1), "r"(a2), "r"(a3), "r"(b0), "r"(b1));
}
static __device__ __forceinline__ float sigf(float t) {
    return 1.f / (1.f + __expf(-t));
}

// ---------------- transpose x [B,L,N] -> xp [N,B,LP] ----------------
__global__ void t1_kernel(const float* __restrict__ x, float* __restrict__ xp) {
    __shared__ float t[32][33];
    const int b = blockIdx.z, n0 = blockIdx.x * 32, l0 = blockIdx.y * 32;
    const int tx = threadIdx.x, ty = threadIdx.y;
    const float* xb = x + (size_t)b * L_ * N_;
#pragma unroll
    for (int i = 0; i < 32; i += 8) {
        int l = l0 + ty + i, nn = n0 + tx;
        t[ty + i][tx] = (l < L_ && nn < N_) ? xb[l * N_ + nn] : 0.f;
    }
    __syncthreads();
#pragma unroll
    for (int i = 0; i < 32; i += 8) {
        int nn = n0 + ty + i, l = l0 + tx;
        if (nn < N_) xp[(size_t)nn * B_ * LP + b * LP + l] = t[tx][ty + i];
    }
}

// ---------------- fused per-(channel, b-half) kernel ----------------
// Mainloop smem (floats): bufA[2] 64x36 @0/2304 ; bufB[2] 32x132 @4608/8832 (end 13056)
// Epilogue smem: stage (hh, A2) 64x132 @0 ; B2 128x68 @8448 (end 17152)
#define SA   36
#define SB   132
#define S2   132
#define SJ   68
#define NC1  11
#define F_A0 0
#define F_A1 2304
#define F_B0 4608
#define F_B1 8832
#define F_STG 0
#define F_B2  8448
#define SM_BYTES (17152 * 4)

__global__ __launch_bounds__(256, 3)
void fused_kernel(const float* __restrict__ xp, const float* __restrict__ We,
                  const float* __restrict__ be, const float* __restrict__ txg,
                  const float* __restrict__ Wmu, const float* __restrict__ bmu,
                  const float* __restrict__ Wvar, const float* __restrict__ bvar,
                  float* __restrict__ out)
{
    extern __shared__ float sm[];
    const uint32_t sb = s2u(sm);
    const int tid = threadIdx.x, wid = tid >> 5, lane = tid & 31;
    const int g = lane >> 2, tg = lane & 3;
    const int n = blockIdx.x;
    const int b0 = blockIdx.y * 64;
    const int m0 = (wid & 1) * 32;      // GEMM1 warp m-base (local row)
    const int n0 = (wid >> 1) * 32;     // GEMM1 warp n-base (e)

    const float* Abase = xp + (size_t)n * B_ * LP + (size_t)b0 * LP;
    const float* Wbase = We + (size_t)n * L_ * E_;

    auto load_chunk = [&](int c, int buf) {
        const int aF = buf ? F_A1 : F_A0;
        const int bF = buf ? F_B1 : F_B0;
#pragma unroll
        for (int i = 0; i < 6; i++) {
            int op = tid + i * 256;          // 0..1535
            if (op < 512) {                  // A: 64 rows x 8 segs
                int m = op >> 3, seg = op & 7;
                uint32_t dst = sb + (uint32_t)(aF + m * SA + seg * 4) * 4u;
                CP16(dst, Abase + m * LP + c * 32 + seg * 4);
            } else {                         // B: 32 l-rows x 32 segs (native [l][e])
                int q = op - 512;
                int row = q >> 5, seg = q & 31;
                int lg = c * 32 + row;
                uint32_t sz = (lg < L_) ? 16u : 0u;
                int lc = (lg < L_) ? lg : (L_ - 1);
                uint32_t dst = sb + (uint32_t)(bF + row * SB + seg * 4) * 4u;
                CP16Z(dst, Wbase + lc * E_ + seg * 4, sz);
            }
        }
        CP_COMMIT();
    };

    float acc[2][4][4];
#pragma unroll
    for (int mi = 0; mi < 2; mi++)
#pragma unroll
        for (int ni = 0; ni < 4; ni++)
#pragma unroll
            for (int r = 0; r < 4; r++) acc[mi][ni][r] = 0.f;

    load_chunk(0, 0);
    load_chunk(1, 1);

    for (int c = 0; c < NC1; c++) {
        const int buf = c & 1;
        if (c + 1 < NC1) CP_WAIT1(); else CP_WAIT0();
        __syncthreads();
        const float* As = sm + (buf ? F_A1 : F_A0);
        const float* Bs = sm + (buf ? F_B1 : F_B0);
#pragma unroll
        for (int s = 0; s < 4; s++) {
            const int k0 = s * 8;
            uint32_t af[2][4];
#pragma unroll
            for (int mi = 0; mi < 2; mi++) {
                const int r0 = m0 + mi * 16 + g;
                af[mi][0] = to_tf32(As[r0 * SA + k0 + tg]);
                af[mi][1] = to_tf32(As[(r0 + 8) * SA + k0 + tg]);
                af[mi][2] = to_tf32(As[r0 * SA + k0 + tg + 4]);
                af[mi][3] = to_tf32(As[(r0 + 8) * SA + k0 + tg + 4]);
            }
#pragma unroll
            for (int ni = 0; ni < 4; ni++) {
                const int nr = n0 + ni * 8 + g;   // e-index
                uint32_t bf0 = to_tf32(Bs[(k0 + tg) * SB + nr]);
                uint32_t bf1 = to_tf32(Bs[(k0 + tg + 4) * SB + nr]);
#pragma unroll
                for (int mi = 0; mi < 2; mi++)
                    mma_tf32(acc[mi][ni], af[mi][0], af[mi][1], af[mi][2], af[mi][3], bf0, bf1);
            }
        }
        __syncthreads();
        if (c + 2 < NC1) load_chunk(c + 2, buf);
    }
    __syncthreads();   // all warps done with mainloop smem

    // prefetch GEMM2 pass-0 B (W_mu native [e][j], 128x64) into B2
    {
        const float* Wsrc = Wmu + (size_t)n * E_ * LAT_;
#pragma unroll
        for (int i = 0; i < 8; i++) {
            int op = tid + i * 256;          // 128 rows x 16 segs
            int row = op >> 4, seg = op & 15;
            uint32_t dst = sb + (uint32_t)(F_B2 + row * SJ + seg * 4) * 4u;
            CP16(dst, Wsrc + row * LAT_ + seg * 4);
        }
        CP_COMMIT();
    }

    // epilogue 1 (register-level): h = acc + bias -> gmem; hh -> gmem + stage
    float* out_h  = out + OFF_H;
    float* out_hh = out + OFF_HH;
#pragma unroll
    for (int mi = 0; mi < 2; mi++) {
#pragma unroll
        for (int ni = 0; ni < 4; ni++) {
            const int col = n0 + ni * 8 + 2 * tg;
            float2 bv = *(const float2*)(be + n * E_ + col);
#pragma unroll
            for (int half = 0; half < 2; half++) {
                const int lr = m0 + mi * 16 + g + half * 8;    // local row
                const int brow = b0 + lr;
                const int o = brow * NE_ + n * E_ + col;
                float2 h;
                h.x = acc[mi][ni][2 * half + 0] + bv.x;
                h.y = acc[mi][ni][2 * half + 1] + bv.y;
                *(float2*)(out_h + o) = h;
                float2 t = *(const float2*)(txg + o);
                float2 hh;
                hh.x = h.x * sigf(t.x);
                hh.y = h.y * sigf(t.y);
                *(float2*)(out_hh + o) = hh;
                *(float2*)(sm + F_STG + lr * S2 + col) = hh;
            }
        }
    }
    CP_WAIT0();
    __syncthreads();

    // GEMM2: two passes over j in [0,64): pass 0 = mu (W_mu), pass 1 = var (W_var)
    const int m2 = (wid & 1) * 32;       // local row base
    const int nt = (wid >> 1) * 16;      // j base (warp tile 32x16)

#pragma unroll
    for (int p = 0; p < 2; p++) {
        if (p == 1) {
            __syncthreads();             // pass-0 reads of B2 done
            const float* Wsrc = Wvar + (size_t)n * E_ * LAT_;
#pragma unroll
            for (int i = 0; i < 8; i++) {
                int op = tid + i * 256;
                int row = op >> 4, seg = op & 15;
                uint32_t dst = sb + (uint32_t)(F_B2 + row * SJ + seg * 4) * 4u;
                CP16(dst, Wsrc + row * LAT_ + seg * 4);
            }
            CP_COMMIT();
            CP_WAIT0();
            __syncthreads();
        }

        float acc2[2][2][4];
#pragma unroll
        for (int mi = 0; mi < 2; mi++)
#pragma unroll
            for (int ni = 0; ni < 2; ni++)
#pragma unroll
                for (int r = 0; r < 4; r++) acc2[mi][ni][r] = 0.f;

        const float* A2 = sm + F_STG;
        const float* B2 = sm + F_B2;
#pragma unroll
        for (int s = 0; s < 16; s++) {
            const int k0 = s * 8;
            uint32_t af[2][4];
#pragma unroll
            for (int mi = 0; mi < 2; mi++) {
                const int r0 = m2 + mi * 16 + g;
                af[mi][0] = to_tf32(A2[r0 * S2 + k0 + tg]);
                af[mi][1] = to_tf32(A2[(r0 + 8) * S2 + k0 + tg]);
                af[mi][2] = to_tf32(A2[r0 * S2 + k0 + tg + 4]);
                af[mi][3] = to_tf32(A2[(r0 + 8) * S2 + k0 + tg + 4]);
            }
#pragma unroll
            for (int ni = 0; ni < 2; ni++) {
                const int j = nt + ni * 8 + g;
                uint32_t bf0 = to_tf32(B2[(k0 + tg) * SJ + j]);
                uint32_t bf1 = to_tf32(B2[(k0 + tg + 4) * SJ + j]);
#pragma unroll
                for (int mi = 0; mi < 2; mi++)
                    mma_tf32(acc2[mi][ni], af[mi][0], af[mi][1], af[mi][2], af[mi][3], bf0, bf1);
            }
        }

        const float* bp = (p ? bvar : bmu) + n * LAT_;
        float* outp = out + (p ? OFF_VAR : OFF_MU);
#pragma unroll
        for (int mi = 0; mi < 2; mi++) {
#pragma unroll
            for (int ni = 0; ni < 2; ni++) {
                const int col = nt + ni * 8 + 2 * tg;
                float2 bv = *(const float2*)(bp + col);
#pragma unroll
                for (int half = 0; half < 2; half++) {
                    const int brow = b0 + m2 + mi * 16 + g + half * 8;
                    float2 v;
                    v.x = acc2[mi][ni][2 * half + 0] + bv.x;
                    v.y = acc2[mi][ni][2 * half + 1] + bv.y;
                    *(float2*)(outp + brow * NL_ + n * LAT_ + col) = v;
                }
            }
        }
    }
}

// ---------------- launch ----------------
extern "C" void kernel_launch(void* const* d_in, const int* in_sizes, int n_in,
                              void* d_out, int out_size) {
    const float* x    = (const float*)d_in[0];
    const float* txg  = (const float*)d_in[1];
    const float* We   = (const float*)d_in[2];
    const float* be   = (const float*)d_in[3];
    const float* Wmu  = (const float*)d_in[4];
    const float* bmu  = (const float*)d_in[5];
    const float* Wvar = (const float*)d_in[6];
    const float* bvar = (const float*)d_in[7];
    float* out = (float*)d_out;

    float* xp;
    cudaGetSymbolAddress((void**)&xp, g_xp);

    cudaFuncSetAttribute(fused_kernel, cudaFuncAttributeMaxDynamicSharedMemorySize, SM_BYTES);

    t1_kernel<<<dim3(11, 11, B_), dim3(32, 8)>>>(x, xp);
    fused_kernel<<<dim3(N_, 2), 256, SM_BYTES>>>(xp, We, be, txg, Wmu, bmu, Wvar, bvar, out);
}

// round 6
// speedup vs baseline: 2.2125x; 1.0532x over previous
#include <cuda_runtime.h>
#include <cstdint>

#define B_   128
#define L_   336
#define LP   352
#define N_   321
#define E_   128
#define LAT_ 64
#define NE_  (N_ * E_)
#define NL_  (N_ * LAT_)

#define H_SZ    (B_ * N_ * E_)
#define MU_SZ   (B_ * N_ * LAT_)
#define OFF_H   0
#define OFF_HH  (H_SZ)
#define OFF_MU  (2 * H_SZ)
#define OFF_VAR (2 * H_SZ + MU_SZ)

__device__ float g_xp[(size_t)N_ * B_ * LP];   // [n][b][l], zero-padded, tf32-rounded

// ---------------- helpers ----------------
static __device__ __forceinline__ uint32_t s2u(const void* p) {
    uint32_t a;
    asm("{ .reg .u64 t; cvta.to.shared.u64 t, %1; cvt.u32.u64 %0, t; }" : "=r"(a) : "l"(p));
    return a;
}
#define CP16(d, s)      asm volatile("cp.async.cg.shared.global [%0], [%1], 16;" :: "r"(d), "l"(s))
#define CP16Z(d, s, sz) asm volatile("cp.async.cg.shared.global [%0], [%1], 16, %2;" :: "r"(d), "l"(s), "r"(sz))
#define CP_COMMIT() asm volatile("cp.async.commit_group;" ::: "memory")
#define CP_WAIT1()  asm volatile("cp.async.wait_group 1;" ::: "memory")
#define CP_WAIT0()  asm volatile("cp.async.wait_group 0;" ::: "memory")

static __device__ __forceinline__ uint32_t to_tf32(float f) {
    uint32_t u;
    asm("cvt.rna.tf32.f32 %0, %1;" : "=r"(u) : "f"(f));
    return u;
}
static __device__ __forceinline__ void mma_tf32(float c[4],
                                                uint32_t a0, uint32_t a1, uint32_t a2, uint32_t a3,
                                                uint32_t b0, uint32_t b1) {
    asm volatile("mma.sync.aligned.m16n8k8.row.col.f32.tf32.tf32.f32 "
                 "{%0,%1,%2,%3}, {%4,%5,%6,%7}, {%8,%9}, {%0,%1,%2,%3};"
                 : "+f"(c[0]), "+f"(c[1]), "+f"(c[2]), "+f"(c[3])
                 : "r"(a0), "r"(a1), "r"(a2), "r"(a3), "r"(b0), "r"(b1));
}
static __device__ __forceinline__ float sigf(float t) {
    return 1.f / (1.f + __expf(-t));
}

// ---------------- transpose x [B,L,N] -> xp [N,B,LP], tf32-rounded ----------------
__global__ void t1_kernel(const float* __restrict__ x, float* __restrict__ xp) {
    __shared__ float t[32][33];
    const int b = blockIdx.z, n0 = blockIdx.x * 32, l0 = blockIdx.y * 32;
    const int tx = threadIdx.x, ty = threadIdx.y;
    const float* xb = x + (size_t)b * L_ * N_;
#pragma unroll
    for (int i = 0; i < 32; i += 8) {
        int l = l0 + ty + i, nn = n0 + tx;
        t[ty + i][tx] = (l < L_ && nn < N_) ? xb[l * N_ + nn] : 0.f;
    }
    __syncthreads();
#pragma unroll
    for (int i = 0; i < 32; i += 8) {
        int nn = n0 + ty + i, l = l0 + tx;
        if (nn < N_)
            xp[(size_t)nn * B_ * LP + b * LP + l] = __uint_as_float(to_tf32(t[tx][ty + i]));
    }
}

// ---------------- fused per-(channel, b-half) kernel ----------------
// Mainloop smem (floats): bufA[2] 64x36 @0/2304 ; bufB[2] 32x128 swz @4608/8704 (end 12800)
// Epilogue smem: stage (hh tf32, A2) 64x132 @0 ; B2 128x64 swz @8448 (end 16640)
#define SA   36
#define S2   132
#define NC1  11
#define F_A0 0
#define F_A1 2304
#define F_B0 4608
#define F_B1 8704
#define F_STG 0
#define F_B2  8448
#define SM_BYTES (16640 * 4)

__global__ __launch_bounds__(256, 3)
void fused_kernel(const float* __restrict__ xp, const float* __restrict__ We,
                  const float* __restrict__ be, const float* __restrict__ txg,
                  const float* __restrict__ Wmu, const float* __restrict__ bmu,
                  const float* __restrict__ Wvar, const float* __restrict__ bvar,
                  float* __restrict__ out)
{
    extern __shared__ float sm[];
    const uint32_t sb = s2u(sm);
    const int tid = threadIdx.x, wid = tid >> 5, lane = tid & 31;
    const int g = lane >> 2, tg = lane & 3;
    const int n = blockIdx.x;
    const int b0 = blockIdx.y * 64;
    const int m0 = (wid & 1) * 32;      // GEMM1 warp m-base (local row)
    const int n0 = (wid >> 1) * 32;     // GEMM1 warp n-base (e)

    const float* Abase = xp + (size_t)n * B_ * LP + (size_t)b0 * LP;
    const float* Wbase = We + (size_t)n * L_ * E_;

    auto load_chunk = [&](int c, int buf) {
        const int aF = buf ? F_A1 : F_A0;
        const int bF = buf ? F_B1 : F_B0;
#pragma unroll
        for (int i = 0; i < 6; i++) {
            int op = tid + i * 256;          // 0..1535
            if (op < 512) {                  // A: 64 rows x 8 segs, stride 36
                int m = op >> 3, seg = op & 7;
                uint32_t dst = sb + (uint32_t)(aF + m * SA + seg * 4) * 4u;
                CP16(dst, Abase + m * LP + c * 32 + seg * 4);
            } else {                         // B: 32 l-rows x 32 segs, stride 128 + XOR swizzle
                int q = op - 512;
                int row = q >> 5, seg = q & 31;
                int lg = c * 32 + row;
                uint32_t sz = (lg < L_) ? 16u : 0u;
                int lc = (lg < L_) ? lg : (L_ - 1);
                int fcol = (seg * 4) ^ ((row & 3) << 3);
                uint32_t dst = sb + (uint32_t)(bF + row * 128 + fcol) * 4u;
                CP16Z(dst, Wbase + lc * E_ + seg * 4, sz);
            }
        }
        CP_COMMIT();
    };

    float acc[2][4][4];
#pragma unroll
    for (int mi = 0; mi < 2; mi++)
#pragma unroll
        for (int ni = 0; ni < 4; ni++)
#pragma unroll
            for (int r = 0; r < 4; r++) acc[mi][ni][r] = 0.f;

    load_chunk(0, 0);
    load_chunk(1, 1);

    const int txg8 = tg << 3;

    for (int c = 0; c < NC1; c++) {
        const int buf = c & 1;
        if (c + 1 < NC1) CP_WAIT1(); else CP_WAIT0();
        __syncthreads();
        const float* As = sm + (buf ? F_A1 : F_A0);
        const float* Bs = sm + (buf ? F_B1 : F_B0);
#pragma unroll
        for (int s = 0; s < 4; s++) {
            const int k0 = s * 8;
            uint32_t af[2][4];
#pragma unroll
            for (int mi = 0; mi < 2; mi++) {
                const int r0 = m0 + mi * 16 + g;
                af[mi][0] = __float_as_uint(As[r0 * SA + k0 + tg]);
                af[mi][1] = __float_as_uint(As[(r0 + 8) * SA + k0 + tg]);
                af[mi][2] = __float_as_uint(As[r0 * SA + k0 + tg + 4]);
                af[mi][3] = __float_as_uint(As[(r0 + 8) * SA + k0 + tg + 4]);
            }
            const float* Br0 = Bs + (k0 + tg) * 128;
            const float* Br1 = Bs + (k0 + tg + 4) * 128;
#pragma unroll
            for (int ni = 0; ni < 4; ni++) {
                const int nj = (n0 + ni * 8 + g) ^ txg8;   // swizzled e-index
                uint32_t bf0 = to_tf32(Br0[nj]);
                uint32_t bf1 = to_tf32(Br1[nj]);
#pragma unroll
                for (int mi = 0; mi < 2; mi++)
                    mma_tf32(acc[mi][ni], af[mi][0], af[mi][1], af[mi][2], af[mi][3], bf0, bf1);
            }
        }
        __syncthreads();
        if (c + 2 < NC1) load_chunk(c + 2, buf);
    }
    __syncthreads();   // all warps done with mainloop smem

    // prefetch GEMM2 pass-0 B (W_mu native [e][j]) into B2, stride 64 + XOR swizzle
    {
        const float* Wsrc = Wmu + (size_t)n * E_ * LAT_;
#pragma unroll
        for (int i = 0; i < 8; i++) {
            int op = tid + i * 256;          // 128 rows x 16 segs
            int row = op >> 4, seg = op & 15;
            int fcol = (seg * 4) ^ ((row & 3) << 3);
            uint32_t dst = sb + (uint32_t)(F_B2 + row * 64 + fcol) * 4u;
            CP16(dst, Wsrc + row * LAT_ + seg * 4);
        }
        CP_COMMIT();
    }

    // epilogue 1: h = acc + bias -> gmem; hh -> gmem (fp32) + stage (tf32-rounded)
    float* out_h  = out + OFF_H;
    float* out_hh = out + OFF_HH;
#pragma unroll
    for (int mi = 0; mi < 2; mi++) {
#pragma unroll
        for (int ni = 0; ni < 4; ni++) {
            const int col = n0 + ni * 8 + 2 * tg;
            float2 bv = *(const float2*)(be + n * E_ + col);
#pragma unroll
            for (int half = 0; half < 2; half++) {
                const int lr = m0 + mi * 16 + g + half * 8;
                const int brow = b0 + lr;
                const int o = brow * NE_ + n * E_ + col;
                float2 h;
                h.x = acc[mi][ni][2 * half + 0] + bv.x;
                h.y = acc[mi][ni][2 * half + 1] + bv.y;
                *(float2*)(out_h + o) = h;
                float2 t = *(const float2*)(txg + o);
                float2 hh;
                hh.x = h.x * sigf(t.x);
                hh.y = h.y * sigf(t.y);
                *(float2*)(out_hh + o) = hh;
                *(float2*)(sm + F_STG + lr * S2 + col) =
                    make_float2(__uint_as_float(to_tf32(hh.x)), __uint_as_float(to_tf32(hh.y)));
            }
        }
    }
    CP_WAIT0();
    __syncthreads();

    // GEMM2: pass 0 = mu (W_mu), pass 1 = var (W_var); j in [0,64)
    const int m2 = (wid & 1) * 32;
    const int nt = (wid >> 1) * 16;

#pragma unroll
    for (int p = 0; p < 2; p++) {
        if (p == 1) {
            __syncthreads();
            const float* Wsrc = Wvar + (size_t)n * E_ * LAT_;
#pragma unroll
            for (int i = 0; i < 8; i++) {
                int op = tid + i * 256;
                int row = op >> 4, seg = op & 15;
                int fcol = (seg * 4) ^ ((row & 3) << 3);
                uint32_t dst = sb + (uint32_t)(F_B2 + row * 64 + fcol) * 4u;
                CP16(dst, Wsrc + row * LAT_ + seg * 4);
            }
            CP_COMMIT();
            CP_WAIT0();
            __syncthreads();
        }

        float acc2[2][2][4];
#pragma unroll
        for (int mi = 0; mi < 2; mi++)
#pragma unroll
            for (int ni = 0; ni < 2; ni++)
#pragma unroll
                for (int r = 0; r < 4; r++) acc2[mi][ni][r] = 0.f;

        const float* A2 = sm + F_STG;
        const float* B2 = sm + F_B2;
#pragma unroll
        for (int s = 0; s < 16; s++) {
            const int k0 = s * 8;
            uint32_t af[2][4];
#pragma unroll
            for (int mi = 0; mi < 2; mi++) {
                const int r0 = m2 + mi * 16 + g;
                af[mi][0] = __float_as_uint(A2[r0 * S2 + k0 + tg]);
                af[mi][1] = __float_as_uint(A2[(r0 + 8) * S2 + k0 + tg]);
                af[mi][2] = __float_as_uint(A2[r0 * S2 + k0 + tg + 4]);
                af[mi][3] = __float_as_uint(A2[(r0 + 8) * S2 + k0 + tg + 4]);
            }
            const float* Br0 = B2 + (k0 + tg) * 64;
            const float* Br1 = B2 + (k0 + tg + 4) * 64;
#pragma unroll
            for (int ni = 0; ni < 2; ni++) {
                const int jn = (nt + ni * 8 + g) ^ txg8;
                uint32_t bf0 = to_tf32(Br0[jn]);
                uint32_t bf1 = to_tf32(Br1[jn]);
#pragma unroll
                for (int mi = 0; mi < 2; mi++)
                    mma_tf32(acc2[mi][ni], af[mi][0], af[mi][1], af[mi][2], af[mi][3], bf0, bf1);
            }
        }

        const float* bp = (p ? bvar : bmu) + n * LAT_;
        float* outp = out + (p ? OFF_VAR : OFF_MU);
#pragma unroll
        for (int mi = 0; mi < 2; mi++) {
#pragma unroll
            for (int ni = 0; ni < 2; ni++) {
                const int col = nt + ni * 8 + 2 * tg;
                float2 bv = *(const float2*)(bp + col);
#pragma unroll
                for (int half = 0; half < 2; half++) {
                    const int brow = b0 + m2 + mi * 16 + g + half * 8;
                    float2 v;
                    v.x = acc2[mi][ni][2 * half + 0] + bv.x;
                    v.y = acc2[mi][ni][2 * half + 1] + bv.y;
                    *(float2*)(outp + brow * NL_ + n * LAT_ + col) = v;
                }
            }
        }
    }
}

// ---------------- launch ----------------
extern "C" void kernel_launch(void* const* d_in, const int* in_sizes, int n_in,
                              void* d_out, int out_size) {
    const float* x    = (const float*)d_in[0];
    const float* txg  = (const float*)d_in[1];
    const float* We   = (const float*)d_in[2];
    const float* be   = (const float*)d_in[3];
    const float* Wmu  = (const float*)d_in[4];
    const float* bmu  = (const float*)d_in[5];
    const float* Wvar = (const float*)d_in[6];
    const float* bvar = (const float*)d_in[7];
    float* out = (float*)d_out;

    float* xp;
    cudaGetSymbolAddress((void**)&xp, g_xp);

    cudaFuncSetAttribute(fused_kernel, cudaFuncAttributeMaxDynamicSharedMemorySize, SM_BYTES);

    t1_kernel<<<dim3(11, 11, B_), dim3(32, 8)>>>(x, xp);
    fused_kernel<<<dim3(N_, 2), 256, SM_BYTES>>>(xp, We, be, txg, Wmu, bmu, Wvar, bvar, out);
}